// round 4
// baseline (speedup 1.0000x reference)
#include <cuda_runtime.h>
#include <cuda_bf16.h>

#define B 64
#define L 1024
#define D 1024
#define S 32

#define DP 2            // d-partitions (CTAs along d); each covers 512 floats
#define DW 512
#define LP 4            // token-chunk partitions (of the SORTED order)
#define LCH (L / LP)    // 256 sorted positions per CTA
#define TPB 128

// Scratch (deterministic: every element written exactly once per launch)
__device__ int   g_perm[B * L];          // tokens grouped by label
__device__ int   g_off[B * (S + 2)];     // label segment offsets (0..33)
__device__ float g_cntf[B * S];          // per-(b,s) token counts
__device__ float g_part[LP * B * S * D]; // 32 MB partial segment sums
__device__ float g_cos[B * S];

// ---------------------------------------------------------------------------
// Kernel 0: deterministic per-batch counting sort of tokens by label.
// ---------------------------------------------------------------------------
__global__ __launch_bounds__(64) void k_sort(const int* __restrict__ attr) {
    __shared__ int slab[L];
    __shared__ int cnt[S + 1];
    __shared__ int off[S + 2];
    const int b = blockIdx.x, tid = threadIdx.x;

    if (tid <= S) cnt[tid] = 0;
    __syncthreads();
    for (int i = tid; i < L; i += 64) {
        int v = attr[b * L + i];
        slab[i] = v;
        atomicAdd(&cnt[v], 1);
    }
    __syncthreads();
    if (tid == 0) {
        int r = 0;
        for (int s = 0; s <= S; s++) { off[s] = r; r += cnt[s]; }
        off[S + 1] = r;  // == L
    }
    __syncthreads();
    if (tid <= S) {            // one thread per label: stable serial fill
        const int lab = tid;
        int pos = off[lab];
        for (int i = 0; i < L; i++)
            if (slab[i] == lab) g_perm[b * L + pos++] = i;
    }
    if (tid <= S + 1) g_off[b * (S + 2) + tid] = off[tid];
    if (tid >= 1 && tid <= S) g_cntf[b * S + tid - 1] = (float)cnt[tid];
}

// ---------------------------------------------------------------------------
// Kernel 1: partial segment sums over sorted runs. Register accumulation,
// float4 loads, one plain store per (label, chunk). No shared RMW.
// ---------------------------------------------------------------------------
__global__ __launch_bounds__(TPB) void k_accum(const float* __restrict__ text) {
    __shared__ int sperm[LCH];
    __shared__ int soff[S + 2];
    const int dp  = blockIdx.x;
    const int b   = blockIdx.y;
    const int lp  = blockIdx.z;
    const int tid = threadIdx.x;
    const int c0  = lp * LCH, c1 = c0 + LCH;

    for (int i = tid; i < LCH; i += TPB) sperm[i] = g_perm[b * L + c0 + i];
    if (tid < S + 2) soff[tid] = g_off[b * (S + 2) + tid];
    __syncthreads();

    const float* tb = text + (size_t)b * L * D + dp * DW + tid * 4;
    float*       ob = g_part + ((size_t)(lp * B + b) * S) * D + dp * DW + tid * 4;

    #pragma unroll 1
    for (int s = 1; s <= S; s++) {
        const int lo = max(soff[s], c0);
        const int hi = min(soff[s + 1], c1);
        float4 a0 = {0,0,0,0}, a1 = {0,0,0,0}, a2 = {0,0,0,0}, a3 = {0,0,0,0};
        int i = lo;
        for (; i + 4 <= hi; i += 4) {
            float4 v0 = __ldcs((const float4*)(tb + (size_t)sperm[i     - c0] * D));
            float4 v1 = __ldcs((const float4*)(tb + (size_t)sperm[i + 1 - c0] * D));
            float4 v2 = __ldcs((const float4*)(tb + (size_t)sperm[i + 2 - c0] * D));
            float4 v3 = __ldcs((const float4*)(tb + (size_t)sperm[i + 3 - c0] * D));
            a0.x += v0.x; a0.y += v0.y; a0.z += v0.z; a0.w += v0.w;
            a1.x += v1.x; a1.y += v1.y; a1.z += v1.z; a1.w += v1.w;
            a2.x += v2.x; a2.y += v2.y; a2.z += v2.z; a2.w += v2.w;
            a3.x += v3.x; a3.y += v3.y; a3.z += v3.z; a3.w += v3.w;
        }
        for (; i < hi; i++) {
            float4 v = __ldcs((const float4*)(tb + (size_t)sperm[i - c0] * D));
            a0.x += v.x; a0.y += v.y; a0.z += v.z; a0.w += v.w;
        }
        float4 r;
        r.x = (a0.x + a1.x) + (a2.x + a3.x);
        r.y = (a0.y + a1.y) + (a2.y + a3.y);
        r.z = (a0.z + a1.z) + (a2.z + a3.z);
        r.w = (a0.w + a1.w) + (a2.w + a3.w);
        *((float4*)(ob + (size_t)(s - 1) * D)) = r;   // empty run -> zeros
    }
}

// ---------------------------------------------------------------------------
// Kernel 2: per-(b,s) cosine similarity; folds the LP partials inline.
// ---------------------------------------------------------------------------
__global__ __launch_bounds__(128) void k_cos(const float* __restrict__ Vgs) {
    const int bs  = blockIdx.x;     // b*S + s
    const int tid = threadIdx.x;

    const float4* vg = (const float4*)(Vgs + (size_t)bs * D);
    const float4* p0 = (const float4*)(g_part + ((size_t)0 * B * S + bs) * D);
    const float4* p1 = (const float4*)(g_part + ((size_t)1 * B * S + bs) * D);
    const float4* p2 = (const float4*)(g_part + ((size_t)2 * B * S + bs) * D);
    const float4* p3 = (const float4*)(g_part + ((size_t)3 * B * S + bs) * D);

    const float cnt = g_cntf[bs];
    const float inv = (cnt > 0.0f) ? (1.0f / cnt) : 0.0f;

    float dvm = 0.0f, dmm = 0.0f, dvv = 0.0f;
    #pragma unroll 2
    for (int d = tid; d < D / 4; d += 128) {
        float4 a0 = p0[d], a1 = p1[d], a2 = p2[d], a3 = p3[d];
        float4 v  = vg[d];
        float mx = ((a0.x + a1.x) + (a2.x + a3.x)) * inv;
        float my = ((a0.y + a1.y) + (a2.y + a3.y)) * inv;
        float mz = ((a0.z + a1.z) + (a2.z + a3.z)) * inv;
        float mw = ((a0.w + a1.w) + (a2.w + a3.w)) * inv;
        dvm = fmaf(v.x, mx, fmaf(v.y, my, fmaf(v.z, mz, fmaf(v.w, mw, dvm))));
        dmm = fmaf(mx, mx, fmaf(my, my, fmaf(mz, mz, fmaf(mw, mw, dmm))));
        dvv = fmaf(v.x, v.x, fmaf(v.y, v.y, fmaf(v.z, v.z, fmaf(v.w, v.w, dvv))));
    }
    #pragma unroll
    for (int o = 16; o > 0; o >>= 1) {
        dvm += __shfl_down_sync(0xFFFFFFFFu, dvm, o);
        dmm += __shfl_down_sync(0xFFFFFFFFu, dmm, o);
        dvv += __shfl_down_sync(0xFFFFFFFFu, dvv, o);
    }
    __shared__ float r0[4], r1[4], r2[4];
    const int w = tid >> 5, lane = tid & 31;
    if (lane == 0) { r0[w] = dvm; r1[w] = dmm; r2[w] = dvv; }
    __syncthreads();
    if (tid == 0) {
        float a  = r0[0] + r0[1] + r0[2] + r0[3];
        float m2 = r1[0] + r1[1] + r1[2] + r1[3];
        float v2 = r2[0] + r2[1] + r2[2] + r2[3];
        float denom = fmaxf(sqrtf(v2) * sqrtf(m2), 1e-8f);
        g_cos[bs] = a / denom;
    }
}

// ---------------------------------------------------------------------------
// Kernel 3: deterministic reduction of 2048 cosines -> scalar loss.
// ---------------------------------------------------------------------------
__global__ __launch_bounds__(1024) void k_final(float* __restrict__ out) {
    const int tid = threadIdx.x;
    float v = g_cos[tid] + g_cos[tid + 1024];
    #pragma unroll
    for (int o = 16; o > 0; o >>= 1) v += __shfl_down_sync(0xFFFFFFFFu, v, o);
    __shared__ float sh[32];
    if ((tid & 31) == 0) sh[tid >> 5] = v;
    __syncthreads();
    if (tid < 32) {
        float x = sh[tid];
        #pragma unroll
        for (int o = 16; o > 0; o >>= 1) x += __shfl_down_sync(0xFFFFFFFFu, x, o);
        if (tid == 0) out[0] = 1.0f - x / (float)(B * S);
    }
}

// ---------------------------------------------------------------------------
extern "C" void kernel_launch(void* const* d_in, const int* in_sizes, int n_in,
                              void* d_out, int out_size) {
    const int*   attr = (const int*)d_in[0];
    const float* text = (const float*)d_in[1];
    const float* vgs  = (const float*)d_in[2];
    float*       out  = (float*)d_out;

    k_sort<<<B, 64>>>(attr);
    dim3 g1(DP, B, LP);
    k_accum<<<g1, TPB>>>(text);
    k_cos<<<B * S, 128>>>(vgs);
    k_final<<<1, 1024>>>(out);
}

// round 7
// speedup vs baseline: 1.2264x; 1.2264x over previous
#include <cuda_runtime.h>
#include <cuda_bf16.h>

#define B 64
#define L 1024
#define D 1024
#define S 32

#define DP 4            // d-partitions; each CTA covers 256 floats (128 float2)
#define DW2 128         // float2 lanes per CTA == TPB
#define LP 4            // token-chunk partitions
#define LCH (L / LP)    // 256 tokens per CTA
#define TPB 128
#define U 8             // tokens per pipelined batch

// Scratch (every element written exactly once per launch -> deterministic)
__device__ float g_part[LP * B * S * D];   // 32 MB partial segment sums
__device__ float g_cntp[B * LP * S];       // per-(b,lp,s) chunk counts
__device__ float g_cos[B * S];

// ---------------------------------------------------------------------------
// Kernel 1: partial segment sums. blockIdx = (d-part, batch, token-chunk).
// Each thread owns one float2 d-column of acc[S][DW2] -> conflict-free,
// race-free scatter-add. Double-buffered batches keep loads always in flight.
// ---------------------------------------------------------------------------
__global__ __launch_bounds__(TPB) void k_accum(const int* __restrict__ attr,
                                               const float* __restrict__ text) {
    __shared__ float2 acc[S * DW2];   // 32 KB
    __shared__ int    slab[LCH];      // 1 KB
    __shared__ int    scnt[S];

    const int dp  = blockIdx.x;
    const int b   = blockIdx.y;
    const int lp  = blockIdx.z;
    const int tid = threadIdx.x;

    #pragma unroll
    for (int i = tid; i < S * DW2; i += TPB) acc[i] = make_float2(0.f, 0.f);
    if (tid < S) scnt[tid] = 0;

    const int* ab = attr + b * L + lp * LCH;
    for (int i = tid; i < LCH; i += TPB) slab[i] = ab[i] - 1;
    __syncthreads();

    // token stride = D/2 float2; this CTA's float2 column = dp*DW2 + tid
    const float2* tb = (const float2*)(text + (size_t)b * L * D
                                            + (size_t)lp * LCH * D)
                       + dp * DW2 + tid;

    float2 v[U]; int sl[U];
    #pragma unroll
    for (int u = 0; u < U; u++) {                 // prefetch batch 0
        v[u]  = __ldcs(tb + (size_t)u * (D / 2));
        sl[u] = slab[u];
    }

    const int NB = LCH / U;
    #pragma unroll 1
    for (int k = 0; k < NB; k++) {
        float2 w[U]; int tl[U];
        if (k + 1 < NB) {                         // prefetch batch k+1 FIRST
            const float2* nb = tb + (size_t)(k + 1) * U * (D / 2);
            #pragma unroll
            for (int u = 0; u < U; u++) {
                w[u]  = __ldcs(nb + (size_t)u * (D / 2));
                tl[u] = slab[(k + 1) * U + u];
            }
        }
        #pragma unroll
        for (int u = 0; u < U; u++) {             // accumulate batch k
            if (sl[u] >= 0) {
                float2* a = &acc[sl[u] * DW2 + tid];
                float2 c = *a;
                c.x += v[u].x; c.y += v[u].y;
                *a = c;
            }
        }
        if (k + 1 < NB) {
            #pragma unroll
            for (int u = 0; u < U; u++) { v[u] = w[u]; sl[u] = tl[u]; }
        }
    }

    // per-chunk counts (dp==0 CTA only; shared atomics, deterministic)
    if (dp == 0) {
        for (int i = tid; i < LCH; i += TPB) {
            int s = slab[i];
            if (s >= 0) atomicAdd(&scnt[s], 1);
        }
    }
    __syncthreads();

    // write this CTA's float2-slice of every partial segment sum
    float2* outp = (float2*)(g_part + ((size_t)lp * B + b) * S * D)
                   + dp * DW2 + tid;
    #pragma unroll
    for (int s = 0; s < S; s++) outp[(size_t)s * (D / 2)] = acc[s * DW2 + tid];
    if (dp == 0 && tid < S) g_cntp[(b * LP + lp) * S + tid] = (float)scnt[tid];
}

// ---------------------------------------------------------------------------
// Kernel 2: per-(b,s) cosine similarity; folds the LP partials inline.
// ---------------------------------------------------------------------------
__global__ __launch_bounds__(128) void k_cos(const float* __restrict__ Vgs) {
    const int bs  = blockIdx.x;     // b*S + s
    const int b   = bs / S;
    const int tid = threadIdx.x;

    const float4* vg = (const float4*)(Vgs + (size_t)bs * D);
    const float4* p0 = (const float4*)(g_part + ((size_t)0 * B * S + bs) * D);
    const float4* p1 = (const float4*)(g_part + ((size_t)1 * B * S + bs) * D);
    const float4* p2 = (const float4*)(g_part + ((size_t)2 * B * S + bs) * D);
    const float4* p3 = (const float4*)(g_part + ((size_t)3 * B * S + bs) * D);

    const int sloc = bs - b * S;
    float cnt = 0.0f;
    #pragma unroll
    for (int lp = 0; lp < LP; lp++) cnt += g_cntp[(b * LP + lp) * S + sloc];
    const float inv = (cnt > 0.0f) ? (1.0f / cnt) : 0.0f;

    float dvm = 0.0f, dmm = 0.0f, dvv = 0.0f;
    #pragma unroll 2
    for (int d = tid; d < D / 4; d += 128) {
        float4 a0 = p0[d], a1 = p1[d], a2 = p2[d], a3 = p3[d];
        float4 v  = vg[d];
        float mx = ((a0.x + a1.x) + (a2.x + a3.x)) * inv;
        float my = ((a0.y + a1.y) + (a2.y + a3.y)) * inv;
        float mz = ((a0.z + a1.z) + (a2.z + a3.z)) * inv;
        float mw = ((a0.w + a1.w) + (a2.w + a3.w)) * inv;
        dvm = fmaf(v.x, mx, fmaf(v.y, my, fmaf(v.z, mz, fmaf(v.w, mw, dvm))));
        dmm = fmaf(mx, mx, fmaf(my, my, fmaf(mz, mz, fmaf(mw, mw, dmm))));
        dvv = fmaf(v.x, v.x, fmaf(v.y, v.y, fmaf(v.z, v.z, fmaf(v.w, v.w, dvv))));
    }
    #pragma unroll
    for (int o = 16; o > 0; o >>= 1) {
        dvm += __shfl_down_sync(0xFFFFFFFFu, dvm, o);
        dmm += __shfl_down_sync(0xFFFFFFFFu, dmm, o);
        dvv += __shfl_down_sync(0xFFFFFFFFu, dvv, o);
    }
    __shared__ float r0[4], r1[4], r2[4];
    const int w = tid >> 5, lane = tid & 31;
    if (lane == 0) { r0[w] = dvm; r1[w] = dmm; r2[w] = dvv; }
    __syncthreads();
    if (tid == 0) {
        float a  = r0[0] + r0[1] + r0[2] + r0[3];
        float m2 = r1[0] + r1[1] + r1[2] + r1[3];
        float v2 = r2[0] + r2[1] + r2[2] + r2[3];
        float denom = fmaxf(sqrtf(v2) * sqrtf(m2), 1e-8f);
        g_cos[bs] = a / denom;
    }
}

// ---------------------------------------------------------------------------
// Kernel 3: deterministic reduction of 2048 cosines -> scalar loss.
// ---------------------------------------------------------------------------
__global__ __launch_bounds__(1024) void k_final(float* __restrict__ out) {
    const int tid = threadIdx.x;
    float v = g_cos[tid] + g_cos[tid + 1024];
    #pragma unroll
    for (int o = 16; o > 0; o >>= 1) v += __shfl_down_sync(0xFFFFFFFFu, v, o);
    __shared__ float sh[32];
    if ((tid & 31) == 0) sh[tid >> 5] = v;
    __syncthreads();
    if (tid < 32) {
        float x = sh[tid];
        #pragma unroll
        for (int o = 16; o > 0; o >>= 1) x += __shfl_down_sync(0xFFFFFFFFu, x, o);
        if (tid == 0) out[0] = 1.0f - x / (float)(B * S);
    }
}

// ---------------------------------------------------------------------------
extern "C" void kernel_launch(void* const* d_in, const int* in_sizes, int n_in,
                              void* d_out, int out_size) {
    const int*   attr = (const int*)d_in[0];
    const float* text = (const float*)d_in[1];
    const float* vgs  = (const float*)d_in[2];
    float*       out  = (float*)d_out;

    dim3 g1(DP, B, LP);
    k_accum<<<g1, TPB>>>(attr, text);
    k_cos<<<B * S, 128>>>(vgs);
    k_final<<<1, 1024>>>(out);
}

// round 8
// speedup vs baseline: 1.2578x; 1.0257x over previous
#include <cuda_runtime.h>
#include <cuda_bf16.h>

#define B 64
#define L 1024
#define D 1024
#define S 32

#define DP 8            // d-partitions; each CTA covers 128 floats
#define DW 128
#define LP 4            // token-chunk partitions
#define LCH (L / LP)    // 256 tokens per CTA
#define TPB 128
#define U 16            // tokens per front-batched load burst

// Scratch (every element written exactly once per launch -> deterministic)
__device__ float g_part[LP * B * S * D];   // 32 MB partial segment sums
__device__ float g_cntp[B * LP * S];       // per-(b,lp,s) chunk counts
__device__ float g_cos[B * S];
__device__ int   g_ctr = 0;                // last-block election; self-resets

// ---------------------------------------------------------------------------
// Kernel 1: partial segment sums. blockIdx = (d-part, batch, token-chunk).
// Thread owns one d-column of acc[S][DW] -> conflict-free scatter-add.
// U=16 front-batched loads: consume in load order so later loads stay in
// flight while earlier ones are accumulated.
// ---------------------------------------------------------------------------
__global__ __launch_bounds__(TPB) void k_accum(const int* __restrict__ attr,
                                               const float* __restrict__ text) {
    __shared__ float       acc[S * DW];    // 16 KB
    __shared__ signed char slab[LCH];      // 256 B (label-1; -1 = skip)
    __shared__ int         scnt[S];

    const int dp  = blockIdx.x;
    const int b   = blockIdx.y;
    const int lp  = blockIdx.z;
    const int tid = threadIdx.x;

    #pragma unroll
    for (int i = tid; i < S * DW; i += TPB) acc[i] = 0.0f;
    if (tid < S) scnt[tid] = 0;

    const int* ab = attr + b * L + lp * LCH;
    for (int i = tid; i < LCH; i += TPB) slab[i] = (signed char)(ab[i] - 1);
    __syncthreads();

    const float* tb = text + (size_t)b * L * D + (size_t)lp * LCH * D
                           + dp * DW + tid;

    #pragma unroll 1
    for (int l = 0; l < LCH; l += U) {
        float v[U];
        #pragma unroll
        for (int u = 0; u < U; u++)
            v[u] = __ldcs(tb + (size_t)(l + u) * D);   // 16 loads in flight
        int lw[U / 4];
        #pragma unroll
        for (int j = 0; j < U / 4; j++)
            lw[j] = ((const int*)slab)[(l >> 2) + j];  // 4 packed labels each
        #pragma unroll
        for (int u = 0; u < U; u++) {                  // consume in load order
            int s = (lw[u >> 2] << (24 - 8 * (u & 3))) >> 24;  // sign-extend
            if (s >= 0) acc[s * DW + tid] += v[u];     // uniform s per warp
        }
    }

    // per-chunk counts (dp==0 CTA only; shared atomics, deterministic)
    if (dp == 0) {
        for (int i = tid; i < LCH; i += TPB) {
            int s = slab[i];
            if (s >= 0) atomicAdd(&scnt[s], 1);
        }
    }
    __syncthreads();

    float* outp = g_part + ((size_t)lp * B + b) * S * D + dp * DW + tid;
    #pragma unroll
    for (int s = 0; s < S; s++) outp[(size_t)s * D] = acc[s * DW + tid];
    if (dp == 0 && tid < S) g_cntp[(b * LP + lp) * S + tid] = (float)scnt[tid];
}

// ---------------------------------------------------------------------------
// Kernel 2: per-(b,s) cosine (folds LP partials) + fused final reduction.
// Last-arriving block reduces all 2048 cosines in a fixed order -> output
// is deterministic regardless of which block is elected.
// ---------------------------------------------------------------------------
__global__ __launch_bounds__(128) void k_cos(const float* __restrict__ Vgs,
                                             float* __restrict__ out) {
    const int bs  = blockIdx.x;     // b*S + s
    const int b   = bs / S;
    const int tid = threadIdx.x;

    const float4* vg = (const float4*)(Vgs + (size_t)bs * D);
    const float4* p0 = (const float4*)(g_part + ((size_t)0 * B * S + bs) * D);
    const float4* p1 = (const float4*)(g_part + ((size_t)1 * B * S + bs) * D);
    const float4* p2 = (const float4*)(g_part + ((size_t)2 * B * S + bs) * D);
    const float4* p3 = (const float4*)(g_part + ((size_t)3 * B * S + bs) * D);

    const int sloc = bs - b * S;
    float cnt = 0.0f;
    #pragma unroll
    for (int lp = 0; lp < LP; lp++) cnt += g_cntp[(b * LP + lp) * S + sloc];
    const float inv = (cnt > 0.0f) ? (1.0f / cnt) : 0.0f;

    float dvm = 0.0f, dmm = 0.0f, dvv = 0.0f;
    #pragma unroll 2
    for (int d = tid; d < D / 4; d += 128) {
        float4 a0 = p0[d], a1 = p1[d], a2 = p2[d], a3 = p3[d];
        float4 v  = vg[d];
        float mx = ((a0.x + a1.x) + (a2.x + a3.x)) * inv;
        float my = ((a0.y + a1.y) + (a2.y + a3.y)) * inv;
        float mz = ((a0.z + a1.z) + (a2.z + a3.z)) * inv;
        float mw = ((a0.w + a1.w) + (a2.w + a3.w)) * inv;
        dvm = fmaf(v.x, mx, fmaf(v.y, my, fmaf(v.z, mz, fmaf(v.w, mw, dvm))));
        dmm = fmaf(mx, mx, fmaf(my, my, fmaf(mz, mz, fmaf(mw, mw, dmm))));
        dvv = fmaf(v.x, v.x, fmaf(v.y, v.y, fmaf(v.z, v.z, fmaf(v.w, v.w, dvv))));
    }
    #pragma unroll
    for (int o = 16; o > 0; o >>= 1) {
        dvm += __shfl_down_sync(0xFFFFFFFFu, dvm, o);
        dmm += __shfl_down_sync(0xFFFFFFFFu, dmm, o);
        dvv += __shfl_down_sync(0xFFFFFFFFu, dvv, o);
    }
    __shared__ float r0[4], r1[4], r2[4];
    const int w = tid >> 5, lane = tid & 31;
    if (lane == 0) { r0[w] = dvm; r1[w] = dmm; r2[w] = dvv; }
    __syncthreads();

    __shared__ int last;
    if (tid == 0) {
        float a  = r0[0] + r0[1] + r0[2] + r0[3];
        float m2 = r1[0] + r1[1] + r1[2] + r1[3];
        float v2 = r2[0] + r2[1] + r2[2] + r2[3];
        float denom = fmaxf(sqrtf(v2) * sqrtf(m2), 1e-8f);
        g_cos[bs] = a / denom;
        __threadfence();
        last = (atomicAdd(&g_ctr, 1) == B * S - 1);
    }
    __syncthreads();

    if (last) {   // fused final reduction, fixed order -> deterministic
        float sum = 0.0f;
        #pragma unroll
        for (int i = tid; i < B * S; i += 128) sum += __ldcg(&g_cos[i]);
        #pragma unroll
        for (int o = 16; o > 0; o >>= 1)
            sum += __shfl_down_sync(0xFFFFFFFFu, sum, o);
        __shared__ float sh[4];
        if (lane == 0) sh[w] = sum;
        __syncthreads();
        if (tid == 0) {
            out[0] = 1.0f - (sh[0] + sh[1] + sh[2] + sh[3]) / (float)(B * S);
            g_ctr = 0;   // reset for next graph replay
        }
    }
}

// ---------------------------------------------------------------------------
extern "C" void kernel_launch(void* const* d_in, const int* in_sizes, int n_in,
                              void* d_out, int out_size) {
    const int*   attr = (const int*)d_in[0];
    const float* text = (const float*)d_in[1];
    const float* vgs  = (const float*)d_in[2];
    float*       out  = (float*)d_out;

    dim3 g1(DP, B, LP);
    k_accum<<<g1, TPB>>>(attr, text);
    k_cos<<<B * S, 128>>>(vgs, out);
}